// round 14
// baseline (speedup 1.0000x reference)
#include <cuda_runtime.h>
#include <cstdint>

#define S_STEPS 19648   // B*N = 64*307 sequential LSTM steps
#define NCH 12          // T_IN: independent LSTM chains
#define HID 128
#define CLS 4           // CTAs per chain-cluster (verified optimum)
#define NROWS_TOTAL (S_STEPS * NCH)

// h history for deferred output projection: 19648*12*128 floats = ~115 MB
__device__ float g_hhist[(size_t)S_STEPS * NCH * HID];

// ---------------- PTX helpers ----------------
__device__ __forceinline__ uint32_t smem_u32(const void* p) {
    uint32_t a;
    asm("{ .reg .u64 t; cvta.to.shared.u64 t, %1; cvt.u32.u64 %0, t; }"
        : "=r"(a) : "l"(p));
    return a;
}
__device__ __forceinline__ uint32_t my_cluster_rank() {
    uint32_t r; asm("mov.u32 %0, %%cluster_ctarank;" : "=r"(r)); return r;
}
__device__ __forceinline__ uint32_t mapa_u32(uint32_t laddr, uint32_t rk) {
    uint32_t r;
    asm("mapa.shared::cluster.u32 %0, %1, %2;" : "=r"(r) : "r"(laddr), "r"(rk));
    return r;
}
// 8-byte remote shared store with mbarrier transaction tracking (proven path).
__device__ __forceinline__ void st_async_b64(uint32_t raddr, unsigned long long v,
                                             uint32_t rmbar) {
    asm volatile(
        "st.async.shared::cluster.mbarrier::complete_tx::bytes.b64 [%0], %1, [%2];"
        :: "r"(raddr), "l"(v), "r"(rmbar) : "memory");
}
#define MBAR_INIT(a, n) \
    asm volatile("mbarrier.init.shared.b64 [%0], %1;" :: "r"(a), "r"((uint32_t)(n)) : "memory")
#define MBAR_EXPECT_TX(a, n) \
    asm volatile("mbarrier.arrive.expect_tx.shared.b64 _, [%0], %1;" :: "r"(a), "r"((uint32_t)(n)) : "memory")
// Proven wait: try_wait.parity.acquire carries st.async data visibility.
#define MBAR_WAIT(a, par) do {                                              \
    asm volatile(                                                           \
        "{\n\t.reg .pred P1;\n\t"                                           \
        "WL_%=:\n\t"                                                        \
        "mbarrier.try_wait.parity.acquire.cta.shared::cta.b64 P1, [%0], %1, 0x989680;\n\t" \
        "@P1 bra.uni WD_%=;\n\t"                                            \
        "bra.uni WL_%=;\n\t"                                                \
        "WD_%=:\n\t}"                                                       \
        :: "r"(a), "r"((uint32_t)(par)) : "memory");                        \
} while (0)

__device__ __forceinline__ unsigned long long fma2(unsigned long long a,
                                                   unsigned long long b,
                                                   unsigned long long c) {
    unsigned long long d;
    asm("fma.rn.f32x2 %0, %1, %2, %3;" : "=l"(d) : "l"(a), "l"(b), "l"(c));
    return d;
}
__device__ __forceinline__ unsigned long long add2(unsigned long long a,
                                                   unsigned long long b) {
    unsigned long long d;
    asm("add.rn.f32x2 %0, %1, %2;" : "=l"(d) : "l"(a), "l"(b));
    return d;
}
__device__ __forceinline__ float unpack_sum(unsigned long long a) {
    uint32_t lo, hi;
    asm("mov.b64 {%0, %1}, %2;" : "=r"(lo), "=r"(hi) : "l"(a));
    return __uint_as_float(lo) + __uint_as_float(hi);
}
__device__ __forceinline__ unsigned long long pack2(float lo, float hi) {
    unsigned long long d;
    asm("mov.b64 %0, {%1, %2};" : "=l"(d) : "f"(lo), "f"(hi));
    return d;
}
__device__ __forceinline__ float tanh_fast(float x) {
    float y; asm("tanh.approx.f32 %0, %1;" : "=f"(y) : "f"(x)); return y;
}
__device__ __forceinline__ float sigmoid_fast(float x) {
    return fmaf(0.5f, tanh_fast(0.5f * x), 0.5f);
}
#define CLUSTER_SYNC() do { \
    asm volatile("barrier.cluster.arrive.aligned;" ::: "memory"); \
    asm volatile("barrier.cluster.wait.aligned;"   ::: "memory"); } while (0)

// ---------------- LSTM kernel ----------------
// 24 CTAs = 6 clusters x 4 CTAs; each cluster runs TWO chains (identical
// weights!) interleaved in time so chain B's gates/sends/own-partials fill
// chain A's DSMEM flight window (~210 cyc idle in the single-chain R12).
// Per chain, per step: byte-identical R12 scheme — lanes 0..11 send b64
// unit-pairs to remote ranks; own-column partial + prefolded x-term (2-step
// x slack) hidden under flight; try_wait; remote 96 columns.
__global__ void __launch_bounds__(128, 1) __cluster_dims__(CLS, 1, 1)
lstm_kernel(const float* __restrict__ x,
            const float* __restrict__ W_ih,
            const float* __restrict__ W_hh,
            const float* __restrict__ b_ih,
            const float* __restrict__ b_hh)
{
    __shared__ __align__(16) float h_sh[2][2][HID];       // [chain][buf][h]
    __shared__ __align__(8)  unsigned long long mbar[2][2]; // [chain][buf]

    const int tid  = threadIdx.x;
    const int w    = tid >> 5;
    const int l    = tid & 31;
    const int rank = (int)my_cluster_rank();
    const int chain0 = 2 * (blockIdx.x / CLS);   // chains chain0, chain0+1

    const int u8  = l & 7;                  // unit within warp's 8
    const int g   = l >> 3;                 // gate 0..3 (i,f,g,o)
    const int ug  = 32 * rank + 8 * w + u8; // global hidden unit
    const int row = g * 128 + ug;           // row in W (4H x H)

    // Register-resident W_hh row (SHARED by both chains): own 32 cols (wl),
    // remote 96 (wr) ordered by rank j=0..2 -> rk=(rank+1+j)&3.
    const ulonglong2* wp =
        reinterpret_cast<const ulonglong2*>(W_hh + (size_t)row * HID);
    ulonglong2 wl[8], wr[24];
    int ob[3];
#pragma unroll
    for (int k = 0; k < 8; k++) wl[k] = wp[rank * 8 + k];
#pragma unroll
    for (int j = 0; j < 3; j++) {
        const int rk = (rank + 1 + j) & 3;
        ob[j] = rk * 128;  // 32 floats * 4B
#pragma unroll
        for (int k = 0; k < 8; k++) wr[j * 8 + k] = wp[rk * 8 + k];
    }

    const float wx0 = W_ih[row * 3 + 0];
    const float wx1 = W_ih[row * 3 + 1];
    const float wx2 = W_ih[row * 3 + 2];
    const float bsum = b_ih[row] + b_hh[row];

    h_sh[0][0][tid] = 0.f;   // 128 threads cover chain0 buf0
    h_sh[1][0][tid] = 0.f;   // chain1 buf0

    uint32_t mb[2][2];
#pragma unroll
    for (int q = 0; q < 2; q++)
#pragma unroll
        for (int bb = 0; bb < 2; bb++)
            mb[q][bb] = smem_u32(&mbar[q][bb]);
    if (tid == 0) {
#pragma unroll
        for (int q = 0; q < 2; q++) {
            MBAR_INIT(mb[q][0], 1);
            MBAR_INIT(mb[q][1], 1);
            MBAR_EXPECT_TX(mb[q][1], 384);  // step-0 sends target buffer 1
        }
    }
    __syncthreads();
    CLUSTER_SYNC();   // mbar init visible cluster-wide before any st.async

    // Send targets (lanes 0..11): pair p=l&3 of this warp's units -> remote
    // rank j=l>>2 (dst=(rank+1+j)&3); per chain.
    const int p_l = l & 3;
    const int dst = (rank + 1 + (l >> 2)) & 3;
    uint32_t mybase[2], dmb0[2], dmb1[2];
    const uint32_t d_h1 = (uint32_t)(HID * sizeof(float)); // buf1 - buf0
#pragma unroll
    for (int q = 0; q < 2; q++) {
        const uint32_t la = smem_u32(&h_sh[q][0][32 * rank + 8 * w + 2 * p_l]);
        mybase[q] = mapa_u32(la, (uint32_t)dst);
        dmb0[q]   = mb[q][0] - la;
        dmb1[q]   = mb[q][1] - la;
    }

    float z[2], c[2] = {0.f, 0.f};
    float xc0[2], xc1[2], xc2[2];
    int ph[2][2] = {{0, 0}, {0, 0}};
    const unsigned fm = 0xffffffffu;

#pragma unroll
    for (int q = 0; q < 2; q++) {
        const int ch = chain0 + q;
        z[q] = bsum + wx0 * x[ch] + wx1 * x[12 + ch] + wx2 * x[24 + ch];
        const float* xp = x + 36 + ch;
        xc0[q] = __ldg(xp); xc1[q] = __ldg(xp + 12); xc2[q] = __ldg(xp + 24);
    }

#define MACRO_STEP(s, P)                                                       \
    {                                                                          \
        const int b = 1 - (P);                                                 \
        if (tid == 0 && (s) > 0 && (s) < S_STEPS - 1) {                        \
            MBAR_EXPECT_TX(mb[0][b], 384);                                     \
            MBAR_EXPECT_TX(mb[1][b], 384);                                     \
        }                                                                      \
        /* prefetch x(s+2), both chains (2-step slack, zero-stall) */          \
        float nx0[2], nx1[2], nx2[2];                                          \
        _Pragma("unroll")                                                      \
        for (int q = 0; q < 2; q++) {                                          \
            nx0[q] = 0.f; nx1[q] = 0.f; nx2[q] = 0.f;                          \
            if ((s) + 2 < S_STEPS) {                                           \
                const float* xp = x + (size_t)((s) + 2) * 36 + chain0 + q;     \
                nx0[q] = __ldg(xp); nx1[q] = __ldg(xp + 12);                   \
                nx2[q] = __ldg(xp + 24);                                       \
            }                                                                  \
        }                                                                      \
        /* PHASE 1: gates + sends + local STS, chain A then chain B.        */ \
        /* B's work issues inside A's DSMEM flight window.                  */ \
        _Pragma("unroll")                                                      \
        for (int q = 0; q < 2; q++) {                                          \
            float zi = __shfl_sync(fm, z[q], u8);                              \
            float zf = __shfl_sync(fm, z[q], u8 + 8);                          \
            float zg = __shfl_sync(fm, z[q], u8 + 16);                         \
            float zo = __shfl_sync(fm, z[q], u8 + 24);                         \
            float si = sigmoid_fast(zi);                                       \
            float sf = sigmoid_fast(zf);                                       \
            float so = sigmoid_fast(zo);                                       \
            c[q] = sf * c[q] + si * tanh_fast(zg);                             \
            float hv = so * tanh_fast(c[q]);                                   \
            float ha = __shfl_sync(fm, hv, 2 * p_l);                           \
            float hb2 = __shfl_sync(fm, hv, 2 * p_l + 1);                      \
            if ((s) + 1 < S_STEPS && l < 12)                                   \
                st_async_b64(mybase[q] + ((b) ? d_h1 : 0u), pack2(ha, hb2),    \
                             mybase[q] + ((b) ? dmb1[q] : dmb0[q]));           \
            if (l < 8) {                                                       \
                h_sh[q][b][ug] = hv;                                           \
                g_hhist[(size_t)((s) * NCH + chain0 + q) * HID + ug] = hv;     \
            }                                                                  \
        }                                                                      \
        __syncthreads();                                                       \
        if ((s) + 1 < S_STEPS) {                                               \
            /* PHASE 2: own-column partials + prefolded x-terms (hidden) */    \
            float zown[2];                                                     \
            _Pragma("unroll")                                                  \
            for (int q = 0; q < 2; q++) {                                      \
                const ulonglong2* hl = reinterpret_cast<const ulonglong2*>(    \
                    (const char*)h_sh[q][b] + rank * 128);                     \
                unsigned long long a0 = 0ull, a1 = 0ull, a2 = 0ull, a3 = 0ull; \
                _Pragma("unroll")                                              \
                for (int k = 0; k < 8; k += 2) {                               \
                    ulonglong2 hA = hl[k];                                     \
                    a0 = fma2(wl[k].x, hA.x, a0);                              \
                    a1 = fma2(wl[k].y, hA.y, a1);                              \
                    ulonglong2 hB = hl[k + 1];                                 \
                    a2 = fma2(wl[k + 1].x, hB.x, a2);                          \
                    a3 = fma2(wl[k + 1].y, hB.y, a3);                          \
                }                                                              \
                zown[q] = unpack_sum(add2(add2(a0, a1), add2(a2, a3)))         \
                        + bsum + wx0 * xc0[q] + wx1 * xc1[q] + wx2 * xc2[q];   \
            }                                                                  \
            /* PHASE 3: wait + remote matvec, chain A then B (B's flight  */   \
            /* completes during A's remote matvec -> fast-path wait).     */   \
            _Pragma("unroll")                                                  \
            for (int q = 0; q < 2; q++) {                                      \
                MBAR_WAIT(mb[q][b], ph[q][b]);                                 \
                ph[q][b] ^= 1;                                                 \
                const char* hb_ = (const char*)h_sh[q][b];                     \
                unsigned long long a4 = 0ull, a5 = 0ull, a6 = 0ull, a7 = 0ull; \
                _Pragma("unroll")                                              \
                for (int j = 0; j < 3; j++) {                                  \
                    const ulonglong2* hr =                                     \
                        reinterpret_cast<const ulonglong2*>(hb_ + ob[j]);      \
                    _Pragma("unroll")                                          \
                    for (int k = 0; k < 8; k += 2) {                           \
                        ulonglong2 hA = hr[k];                                 \
                        a4 = fma2(wr[j * 8 + k].x, hA.x, a4);                  \
                        a5 = fma2(wr[j * 8 + k].y, hA.y, a5);                  \
                        ulonglong2 hB = hr[k + 1];                             \
                        a6 = fma2(wr[j * 8 + k + 1].x, hB.x, a6);              \
                        a7 = fma2(wr[j * 8 + k + 1].y, hB.y, a7);              \
                    }                                                          \
                }                                                              \
                z[q] = zown[q] + unpack_sum(add2(add2(a4, a5), add2(a6, a7))); \
            }                                                                  \
        }                                                                      \
        _Pragma("unroll")                                                      \
        for (int q = 0; q < 2; q++) {                                          \
            xc0[q] = nx0[q]; xc1[q] = nx1[q]; xc2[q] = nx2[q];                 \
        }                                                                      \
    }

    for (int s = 0; s < S_STEPS; s += 2) {
        MACRO_STEP(s, 0);
        MACRO_STEP(s + 1, 1);
    }
#undef MACRO_STEP
}

// Deferred output projection: out[row] = b_lin + h_hist[row,:] . W_lin
__global__ void __launch_bounds__(256) out_kernel(
    const float* __restrict__ Wlin, const float* __restrict__ blin,
    float* __restrict__ out)
{
    const int lane = threadIdx.x & 31;
    const int warp = (blockIdx.x * blockDim.x + threadIdx.x) >> 5;
    const float w0 = Wlin[lane],      w1 = Wlin[lane + 32];
    const float w2 = Wlin[lane + 64], w3 = Wlin[lane + 96];
    const float bl = __ldg(blin);
    int row = warp * 8;
#pragma unroll
    for (int k = 0; k < 8; k++, row++) {
        if (row >= NROWS_TOTAL) return;
        const float* h = g_hhist + (size_t)row * HID;
        float s = h[lane] * w0 + h[lane + 32] * w1
                + h[lane + 64] * w2 + h[lane + 96] * w3;
#pragma unroll
        for (int off = 16; off; off >>= 1)
            s += __shfl_xor_sync(0xffffffffu, s, off);
        if (lane == 0) out[row] = s + bl;
    }
}

extern "C" void kernel_launch(void* const* d_in, const int* in_sizes, int n_in,
                              void* d_out, int out_size)
{
    const float* x     = (const float*)d_in[0];
    const float* W_ih  = (const float*)d_in[1];
    const float* W_hh  = (const float*)d_in[2];
    const float* b_ih  = (const float*)d_in[3];
    const float* b_hh  = (const float*)d_in[4];
    const float* W_lin = (const float*)d_in[5];
    const float* b_lin = (const float*)d_in[6];
    float* out = (float*)d_out;

    // 6 clusters x 4 CTAs, 2 chains per cluster
    lstm_kernel<<<6 * CLS, 128>>>(x, W_ih, W_hh, b_ih, b_hh);
    out_kernel<<<3684, 256>>>(W_lin, b_lin, out);
}

// round 15
// speedup vs baseline: 1.1872x; 1.1872x over previous
#include <cuda_runtime.h>
#include <cstdint>

#define S_STEPS 19648   // B*N = 64*307 sequential LSTM steps
#define NCH 12          // T_IN: independent LSTM chains
#define HID 128
#define CLS 4           // CTAs per cluster (verified optimum)
#define NROWS_TOTAL (S_STEPS * NCH)

// h history for deferred output projection: 19648*12*128 floats = ~115 MB
__device__ float g_hhist[(size_t)S_STEPS * NCH * HID];

// ---------------- PTX helpers ----------------
__device__ __forceinline__ uint32_t smem_u32(const void* p) {
    uint32_t a;
    asm("{ .reg .u64 t; cvta.to.shared.u64 t, %1; cvt.u32.u64 %0, t; }"
        : "=r"(a) : "l"(p));
    return a;
}
__device__ __forceinline__ uint32_t my_cluster_rank() {
    uint32_t r; asm("mov.u32 %0, %%cluster_ctarank;" : "=r"(r)); return r;
}
__device__ __forceinline__ uint32_t mapa_u32(uint32_t laddr, uint32_t rk) {
    uint32_t r;
    asm("mapa.shared::cluster.u32 %0, %1, %2;" : "=r"(r) : "r"(laddr), "r"(rk));
    return r;
}
// 8-byte remote shared store with mbarrier transaction tracking (proven path).
__device__ __forceinline__ void st_async_b64(uint32_t raddr, unsigned long long v,
                                             uint32_t rmbar) {
    asm volatile(
        "st.async.shared::cluster.mbarrier::complete_tx::bytes.b64 [%0], %1, [%2];"
        :: "r"(raddr), "l"(v), "r"(rmbar) : "memory");
}
#define MBAR_INIT(a, n) \
    asm volatile("mbarrier.init.shared.b64 [%0], %1;" :: "r"(a), "r"((uint32_t)(n)) : "memory")
#define MBAR_EXPECT_TX(a, n) \
    asm volatile("mbarrier.arrive.expect_tx.shared.b64 _, [%0], %1;" :: "r"(a), "r"((uint32_t)(n)) : "memory")
// Proven wait: try_wait.parity.acquire carries st.async data visibility.
#define MBAR_WAIT(a, par) do {                                              \
    asm volatile(                                                           \
        "{\n\t.reg .pred P1;\n\t"                                           \
        "WL_%=:\n\t"                                                        \
        "mbarrier.try_wait.parity.acquire.cta.shared::cta.b64 P1, [%0], %1, 0x989680;\n\t" \
        "@P1 bra.uni WD_%=;\n\t"                                            \
        "bra.uni WL_%=;\n\t"                                                \
        "WD_%=:\n\t}"                                                       \
        :: "r"(a), "r"((uint32_t)(par)) : "memory");                        \
} while (0)
// Per-chain-group barrier: 128 threads, id 1 or 2.
#define GROUP_BAR(id) \
    asm volatile("bar.sync %0, 128;" :: "r"(id) : "memory")

__device__ __forceinline__ unsigned long long fma2(unsigned long long a,
                                                   unsigned long long b,
                                                   unsigned long long c) {
    unsigned long long d;
    asm("fma.rn.f32x2 %0, %1, %2, %3;" : "=l"(d) : "l"(a), "l"(b), "l"(c));
    return d;
}
__device__ __forceinline__ unsigned long long add2(unsigned long long a,
                                                   unsigned long long b) {
    unsigned long long d;
    asm("add.rn.f32x2 %0, %1, %2;" : "=l"(d) : "l"(a), "l"(b));
    return d;
}
__device__ __forceinline__ float unpack_sum(unsigned long long a) {
    uint32_t lo, hi;
    asm("mov.b64 {%0, %1}, %2;" : "=r"(lo), "=r"(hi) : "l"(a));
    return __uint_as_float(lo) + __uint_as_float(hi);
}
__device__ __forceinline__ unsigned long long pack2(float lo, float hi) {
    unsigned long long d;
    asm("mov.b64 %0, {%1, %2};" : "=l"(d) : "f"(lo), "f"(hi));
    return d;
}
__device__ __forceinline__ float tanh_fast(float x) {
    float y; asm("tanh.approx.f32 %0, %1;" : "=f"(y) : "f"(x)); return y;
}
__device__ __forceinline__ float sigmoid_fast(float x) {
    return fmaf(0.5f, tanh_fast(0.5f * x), 0.5f);
}
#define CLUSTER_SYNC() do { \
    asm volatile("barrier.cluster.arrive.aligned;" ::: "memory"); \
    asm volatile("barrier.cluster.wait.aligned;"   ::: "memory"); } while (0)

// ---------------- LSTM kernel ----------------
// 24 CTAs = 6 clusters x 4 CTAs, 256 threads/CTA. Warps 0-3 run chain A,
// warps 4-7 run chain B (identical weights, zero extra per-thread state).
// Each 128-thread group is an EXACT R12 pipeline: CTA rank r owns units
// [32r,32r+32) of its chain; one full gate row per thread; b64 pair sends
// (lanes<12) pre-bar; own-column partial + prefolded x-term (2-step slack)
// hidden under the DSMEM flight; try_wait; remote 96 columns.
// The warp scheduler overlaps the two groups: while one chain sleeps in
// try_wait (~290 cyc/step idle in R12), the other issues its ~380 cyc.
__global__ void __launch_bounds__(256, 1) __cluster_dims__(CLS, 1, 1)
lstm_kernel(const float* __restrict__ x,
            const float* __restrict__ W_ih,
            const float* __restrict__ W_hh,
            const float* __restrict__ b_ih,
            const float* __restrict__ b_hh)
{
    __shared__ __align__(16) float h_sh[2][2][HID];         // [group][buf][h]
    __shared__ __align__(8)  unsigned long long mbar[2][2]; // [group][buf]

    const int tid  = threadIdx.x;
    const int cg   = tid >> 7;       // chain group 0/1 (warps 0-3 / 4-7)
    const int wt   = tid & 127;      // thread id within group
    const int w    = wt >> 5;        // warp within group
    const int l    = wt & 31;
    const int rank = (int)my_cluster_rank();
    const int chain = 2 * (blockIdx.x / CLS) + cg;
    const int barid = 1 + cg;        // named barrier per group

    const int u8  = l & 7;                  // unit within warp's 8
    const int g   = l >> 3;                 // gate 0..3 (i,f,g,o)
    const int ug  = 32 * rank + 8 * w + u8; // hidden unit (within chain)
    const int row = g * 128 + ug;           // row in W (4H x H)

    // Register-resident W_hh row (same for both groups): own 32 cols (wl),
    // remote 96 (wr) ordered by remote rank j=0..2 -> rk=(rank+1+j)&3.
    const ulonglong2* wp =
        reinterpret_cast<const ulonglong2*>(W_hh + (size_t)row * HID);
    ulonglong2 wl[8], wr[24];
    int ob[3];
#pragma unroll
    for (int k = 0; k < 8; k++) wl[k] = wp[rank * 8 + k];
#pragma unroll
    for (int j = 0; j < 3; j++) {
        const int rk = (rank + 1 + j) & 3;
        ob[j] = rk * 128;  // 32 floats * 4B
#pragma unroll
        for (int k = 0; k < 8; k++) wr[j * 8 + k] = wp[rk * 8 + k];
    }

    const float wx0 = W_ih[row * 3 + 0];
    const float wx1 = W_ih[row * 3 + 1];
    const float wx2 = W_ih[row * 3 + 2];
    const float bsum = b_ih[row] + b_hh[row];

    h_sh[cg][0][wt] = 0.f;   // each group zeros its own buffer 0

    const uint32_t mb_l0 = smem_u32(&mbar[cg][0]);
    const uint32_t mb_l1 = smem_u32(&mbar[cg][1]);
    if (tid == 0) {
#pragma unroll
        for (int q = 0; q < 2; q++) {
            MBAR_INIT(smem_u32(&mbar[q][0]), 1);
            MBAR_INIT(smem_u32(&mbar[q][1]), 1);
            MBAR_EXPECT_TX(smem_u32(&mbar[q][1]), 384); // step-0 -> buf/mbar 1
        }
    }
    __syncthreads();   // zeros + mbar init (both groups) done
    CLUSTER_SYNC();    // visible cluster-wide before any st.async

    // Send targets (lanes 0..11): pair p=l&3 of this warp's units -> remote
    // rank j=l>>2 (dst=(rank+1+j)&3), within THIS group's h/mbar.
    const int p_l = l & 3;
    const int dst = (rank + 1 + (l >> 2)) & 3;
    const uint32_t la_pair = smem_u32(&h_sh[cg][0][32 * rank + 8 * w + 2 * p_l]);
    const uint32_t mybase  = mapa_u32(la_pair, (uint32_t)dst);
    const uint32_t d_h1    = (uint32_t)(HID * sizeof(float));
    const uint32_t d_mb0   = mb_l0 - la_pair;
    const uint32_t d_mb1   = mb_l1 - la_pair;

    float c = 0.f;        // cell state (replicated across lanes; valid for u8)
    int ph0 = 0, ph1 = 0; // mbarrier phase parities
    const unsigned fm = 0xffffffffu;

    // Step-0 pre-activation: h(-1)=0, so z = bsum + W_ih . x(0)
    float z = bsum + wx0 * x[chain] + wx1 * x[12 + chain] + wx2 * x[24 + chain];

    // Carried x for step 1 (consumed in step 0's hidden window) — full slack
    float xc0 = 0.f, xc1 = 0.f, xc2 = 0.f;
    {
        const float* xp = x + 36 + chain;
        xc0 = __ldg(xp); xc1 = __ldg(xp + 12); xc2 = __ldg(xp + 24);
    }

#define LSTM_STEP(s, P)                                                        \
    {                                                                          \
        const int b = 1 - (P);                                                 \
        if (wt == 0 && (s) > 0 && (s) < S_STEPS - 1)                           \
            MBAR_EXPECT_TX((b) ? mb_l1 : mb_l0, 384);                          \
        /* prefetch x(s+2): consumed in step s+1's hidden window */            \
        float nx0 = 0.f, nx1 = 0.f, nx2 = 0.f;                                 \
        if ((s) + 2 < S_STEPS) {                                               \
            const float* xp = x + (size_t)((s) + 2) * 36 + chain;              \
            nx0 = __ldg(xp); nx1 = __ldg(xp + 12); nx2 = __ldg(xp + 24);       \
        }                                                                      \
        /* gates from carried z; computed on ALL lanes (c replicated) */       \
        float zi = __shfl_sync(fm, z, u8);                                     \
        float zf = __shfl_sync(fm, z, u8 + 8);                                 \
        float zg = __shfl_sync(fm, z, u8 + 16);                                \
        float zo = __shfl_sync(fm, z, u8 + 24);                                \
        float si = sigmoid_fast(zi);                                           \
        float sf = sigmoid_fast(zf);                                           \
        float so = sigmoid_fast(zo);                                           \
        c = sf * c + si * tanh_fast(zg);                                       \
        float hv = so * tanh_fast(c);                                          \
        /* fire remote sends ASAP: pair (h[2p], h[2p+1]) to rank dst */        \
        float ha = __shfl_sync(fm, hv, 2 * p_l);                               \
        float hb2 = __shfl_sync(fm, hv, 2 * p_l + 1);                          \
        if ((s) + 1 < S_STEPS && l < 12)                                       \
            st_async_b64(mybase + ((b) ? d_h1 : 0u), pack2(ha, hb2),           \
                         mybase + ((b) ? d_mb1 : d_mb0));                      \
        /* own h: plain local STS (no flight) + history store */               \
        if (l < 8) {                                                           \
            h_sh[cg][b][ug] = hv;                                              \
            g_hhist[(size_t)((s) * NCH + chain) * HID + ug] = hv;              \
        }                                                                      \
        GROUP_BAR(barid);   /* per-group barrier (128 threads) */              \
        if ((s) + 1 < S_STEPS) {                                               \
            /* hidden under flight: own-column partial (16 fma2) + prefold */  \
            const char* hb_ = (const char*)h_sh[cg][b];                        \
            const ulonglong2* hl =                                             \
                reinterpret_cast<const ulonglong2*>(hb_ + rank * 128);         \
            unsigned long long a0 = 0ull, a1 = 0ull, a2 = 0ull, a3 = 0ull;     \
            _Pragma("unroll")                                                  \
            for (int k = 0; k < 8; k += 2) {                                   \
                ulonglong2 hA = hl[k];                                         \
                a0 = fma2(wl[k].x, hA.x, a0);                                  \
                a1 = fma2(wl[k].y, hA.y, a1);                                  \
                ulonglong2 hB = hl[k + 1];                                     \
                a2 = fma2(wl[k + 1].x, hB.x, a2);                              \
                a3 = fma2(wl[k + 1].y, hB.y, a3);                              \
            }                                                                  \
            float zown = unpack_sum(add2(add2(a0, a1), add2(a2, a3)))          \
                       + bsum + wx0 * xc0 + wx1 * xc1 + wx2 * xc2;             \
            /* wait for the 3 remote ranks' h (384B into this group's mbar) */ \
            if (b) { MBAR_WAIT(mb_l1, ph1); ph1 ^= 1; }                        \
            else   { MBAR_WAIT(mb_l0, ph0); ph0 ^= 1; }                        \
            /* remote 96 columns: 3 blocks x 16 fma2 */                        \
            unsigned long long a4 = 0ull, a5 = 0ull, a6 = 0ull, a7 = 0ull;     \
            _Pragma("unroll")                                                  \
            for (int j = 0; j < 3; j++) {                                      \
                const ulonglong2* hr =                                         \
                    reinterpret_cast<const ulonglong2*>(hb_ + ob[j]);          \
                _Pragma("unroll")                                              \
                for (int k = 0; k < 8; k += 2) {                               \
                    ulonglong2 hA = hr[k];                                     \
                    a4 = fma2(wr[j * 8 + k].x, hA.x, a4);                      \
                    a5 = fma2(wr[j * 8 + k].y, hA.y, a5);                      \
                    ulonglong2 hB = hr[k + 1];                                 \
                    a6 = fma2(wr[j * 8 + k + 1].x, hB.x, a6);                  \
                    a7 = fma2(wr[j * 8 + k + 1].y, hB.y, a7);                  \
                }                                                              \
            }                                                                  \
            z = zown + unpack_sum(add2(add2(a4, a5), add2(a6, a7)));           \
        }                                                                      \
        xc0 = nx0; xc1 = nx1; xc2 = nx2;                                       \
    }

    for (int s = 0; s < S_STEPS; s += 2) {
        LSTM_STEP(s, 0);
        LSTM_STEP(s + 1, 1);
    }
#undef LSTM_STEP
}

// Deferred output projection: out[row] = b_lin + h_hist[row,:] . W_lin
__global__ void __launch_bounds__(256) out_kernel(
    const float* __restrict__ Wlin, const float* __restrict__ blin,
    float* __restrict__ out)
{
    const int lane = threadIdx.x & 31;
    const int warp = (blockIdx.x * blockDim.x + threadIdx.x) >> 5;
    const float w0 = Wlin[lane],      w1 = Wlin[lane + 32];
    const float w2 = Wlin[lane + 64], w3 = Wlin[lane + 96];
    const float bl = __ldg(blin);
    int row = warp * 8;
#pragma unroll
    for (int k = 0; k < 8; k++, row++) {
        if (row >= NROWS_TOTAL) return;
        const float* h = g_hhist + (size_t)row * HID;
        float s = h[lane] * w0 + h[lane + 32] * w1
                + h[lane + 64] * w2 + h[lane + 96] * w3;
#pragma unroll
        for (int off = 16; off; off >>= 1)
            s += __shfl_xor_sync(0xffffffffu, s, off);
        if (lane == 0) out[row] = s + bl;
    }
}

extern "C" void kernel_launch(void* const* d_in, const int* in_sizes, int n_in,
                              void* d_out, int out_size)
{
    const float* x     = (const float*)d_in[0];
    const float* W_ih  = (const float*)d_in[1];
    const float* W_hh  = (const float*)d_in[2];
    const float* b_ih  = (const float*)d_in[3];
    const float* b_hh  = (const float*)d_in[4];
    const float* W_lin = (const float*)d_in[5];
    const float* b_lin = (const float*)d_in[6];
    float* out = (float*)d_out;

    // 6 clusters x 4 CTAs, 256 threads: warps 0-3 chain A, warps 4-7 chain B
    lstm_kernel<<<6 * CLS, 256>>>(x, W_ih, W_hh, b_ih, b_hh);
    out_kernel<<<3684, 256>>>(W_lin, b_lin, out);
}

// round 16
// speedup vs baseline: 1.7131x; 1.4430x over previous
#include <cuda_runtime.h>
#include <cstdint>

#define S_STEPS 19648   // B*N = 64*307 sequential LSTM steps
#define NCH 12          // T_IN: independent LSTM chains
#define HID 128
#define CLS 4           // CTAs per chain (cluster size) — verified optimum
#define NROWS_TOTAL (S_STEPS * NCH)

// h history for deferred output projection: 19648*12*128 floats = ~115 MB
__device__ float g_hhist[(size_t)S_STEPS * NCH * HID];

// ---------------- PTX helpers ----------------
__device__ __forceinline__ uint32_t smem_u32(const void* p) {
    uint32_t a;
    asm("{ .reg .u64 t; cvta.to.shared.u64 t, %1; cvt.u32.u64 %0, t; }"
        : "=r"(a) : "l"(p));
    return a;
}
__device__ __forceinline__ uint32_t my_cluster_rank() {
    uint32_t r; asm("mov.u32 %0, %%cluster_ctarank;" : "=r"(r)); return r;
}
__device__ __forceinline__ uint32_t mapa_u32(uint32_t laddr, uint32_t rk) {
    uint32_t r;
    asm("mapa.shared::cluster.u32 %0, %1, %2;" : "=r"(r) : "r"(laddr), "r"(rk));
    return r;
}
// 8-byte remote shared store with mbarrier transaction tracking (proven path).
__device__ __forceinline__ void st_async_b64(uint32_t raddr, unsigned long long v,
                                             uint32_t rmbar) {
    asm volatile(
        "st.async.shared::cluster.mbarrier::complete_tx::bytes.b64 [%0], %1, [%2];"
        :: "r"(raddr), "l"(v), "r"(rmbar) : "memory");
}
#define MBAR_INIT(a, n) \
    asm volatile("mbarrier.init.shared.b64 [%0], %1;" :: "r"(a), "r"((uint32_t)(n)) : "memory")
#define MBAR_EXPECT_TX(a, n) \
    asm volatile("mbarrier.arrive.expect_tx.shared.b64 _, [%0], %1;" :: "r"(a), "r"((uint32_t)(n)) : "memory")
// Proven wait: try_wait.parity.acquire carries st.async data visibility.
#define MBAR_WAIT(a, par) do {                                              \
    asm volatile(                                                           \
        "{\n\t.reg .pred P1;\n\t"                                           \
        "WL_%=:\n\t"                                                        \
        "mbarrier.try_wait.parity.acquire.cta.shared::cta.b64 P1, [%0], %1, 0x989680;\n\t" \
        "@P1 bra.uni WD_%=;\n\t"                                            \
        "bra.uni WL_%=;\n\t"                                                \
        "WD_%=:\n\t}"                                                       \
        :: "r"(a), "r"((uint32_t)(par)) : "memory");                        \
} while (0)

__device__ __forceinline__ unsigned long long fma2(unsigned long long a,
                                                   unsigned long long b,
                                                   unsigned long long c) {
    unsigned long long d;
    asm("fma.rn.f32x2 %0, %1, %2, %3;" : "=l"(d) : "l"(a), "l"(b), "l"(c));
    return d;
}
__device__ __forceinline__ unsigned long long add2(unsigned long long a,
                                                   unsigned long long b) {
    unsigned long long d;
    asm("add.rn.f32x2 %0, %1, %2;" : "=l"(d) : "l"(a), "l"(b));
    return d;
}
__device__ __forceinline__ float unpack_sum(unsigned long long a) {
    uint32_t lo, hi;
    asm("mov.b64 {%0, %1}, %2;" : "=r"(lo), "=r"(hi) : "l"(a));
    return __uint_as_float(lo) + __uint_as_float(hi);
}
__device__ __forceinline__ unsigned long long pack2(float lo, float hi) {
    unsigned long long d;
    asm("mov.b64 %0, {%1, %2};" : "=l"(d) : "f"(lo), "f"(hi));
    return d;
}
__device__ __forceinline__ float tanh_fast(float x) {
    float y; asm("tanh.approx.f32 %0, %1;" : "=f"(y) : "f"(x)); return y;
}
__device__ __forceinline__ float sigmoid_fast(float x) {
    return fmaf(0.5f, tanh_fast(0.5f * x), 0.5f);
}
#define CLUSTER_SYNC() do { \
    asm volatile("barrier.cluster.arrive.aligned;" ::: "memory"); \
    asm volatile("barrier.cluster.wait.aligned;"   ::: "memory"); } while (0)

// ---------------- LSTM kernel ----------------
// 48 CTAs = 12 chains x 4-CTA clusters, 128 threads/CTA (1 warp per SMSP).
// CTA rank r owns hidden units [32r, 32r+32); one FULL gate row per thread:
//   lane l: unit u8 = l&7 (warp w owns units 8w..8w+7), gate g = l>>3
// Proven R12 pipeline with two tail micro-optimizations:
//  (1) zown (own-column partial + bsum + W_ih.xc) fully folded BEFORE the
//      mbarrier wait (hidden window) — removes ~25 cyc from the exposed tail.
//  (2) g_hhist STG moved after __syncthreads into the hidden window.
// x pipelined TWO steps (xc slack) — NAT-clock L2 latency is ~450 cyc.
__global__ void __launch_bounds__(128, 1) __cluster_dims__(CLS, 1, 1)
lstm_kernel(const float* __restrict__ x,
            const float* __restrict__ W_ih,
            const float* __restrict__ W_hh,
            const float* __restrict__ b_ih,
            const float* __restrict__ b_hh)
{
    __shared__ __align__(16) float h_sh[2][HID];   // double-buffered hidden state
    __shared__ __align__(8)  unsigned long long mbar[2];

    const int tid  = threadIdx.x;
    const int w    = tid >> 5;
    const int l    = tid & 31;
    const int rank = (int)my_cluster_rank();
    const int chain = blockIdx.x / CLS;

    const int u8  = l & 7;                  // unit within warp's 8
    const int g   = l >> 3;                 // gate 0..3 (i,f,g,o)
    const int ug  = 32 * rank + 8 * w + u8; // global hidden unit
    const int row = g * 128 + ug;           // row in W (4H x H)

    // Register-resident W_hh row, split: own 32 cols (wl) / remote 96 (wr),
    // wr ordered by remote rank j=0..2 -> rk=(rank+1+j)&3, cols [32rk,32rk+32)
    const ulonglong2* wp =
        reinterpret_cast<const ulonglong2*>(W_hh + (size_t)row * HID);
    ulonglong2 wl[8], wr[24];
    int ob[3];  // byte offsets of remote column blocks within h row
#pragma unroll
    for (int k = 0; k < 8; k++) wl[k] = wp[rank * 8 + k];
#pragma unroll
    for (int j = 0; j < 3; j++) {
        const int rk = (rank + 1 + j) & 3;
        ob[j] = rk * 128;  // 32 floats * 4B
#pragma unroll
        for (int k = 0; k < 8; k++) wr[j * 8 + k] = wp[rk * 8 + k];
    }

    const float wx0 = W_ih[row * 3 + 0];
    const float wx1 = W_ih[row * 3 + 1];
    const float wx2 = W_ih[row * 3 + 2];
    const float bsum = b_ih[row] + b_hh[row];

    h_sh[0][tid] = 0.f;   // 128 threads cover all 128 h

    const uint32_t mb_l0 = smem_u32(&mbar[0]);
    const uint32_t mb_l1 = smem_u32(&mbar[1]);
    if (tid == 0) {
        MBAR_INIT(mb_l0, 1);
        MBAR_INIT(mb_l1, 1);
        MBAR_EXPECT_TX(mb_l1, 384);   // step-0 sends target buffer/mbar 1
    }
    __syncthreads();   // local h zeros + mbar init done
    CLUSTER_SYNC();    // mbar init visible cluster-wide before any st.async

    // Send targets (lanes 0..11): pair p=l&3 of this warp's units -> remote
    // rank j=l>>2 (dst = (rank+1+j)&3). Buffer-1/mbar addrs by const deltas.
    const int p_l = l & 3;
    const int dst = (rank + 1 + (l >> 2)) & 3;
    const uint32_t la_pair = smem_u32(&h_sh[0][32 * rank + 8 * w + 2 * p_l]);
    const uint32_t mybase  = mapa_u32(la_pair, (uint32_t)dst);
    const uint32_t d_h1    = (uint32_t)(HID * sizeof(float));
    const uint32_t d_mb0   = mb_l0 - la_pair;
    const uint32_t d_mb1   = mb_l1 - la_pair;

    float c = 0.f;        // cell state (replicated across lanes; valid for u8)
    int ph0 = 0, ph1 = 0; // mbarrier phase parities
    const unsigned fm = 0xffffffffu;

    // Step-0 pre-activation: h(-1)=0, so z = bsum + W_ih . x(0)
    float z = bsum + wx0 * x[chain] + wx1 * x[12 + chain] + wx2 * x[24 + chain];

    // Carried x for step 1 (consumed in step 0's hidden window) — full slack
    float xc0 = 0.f, xc1 = 0.f, xc2 = 0.f;
    {
        const float* xp = x + 36 + chain;
        xc0 = __ldg(xp); xc1 = __ldg(xp + 12); xc2 = __ldg(xp + 24);
    }

#define LSTM_STEP(s, P)                                                        \
    {                                                                          \
        const int b = 1 - (P);                                                 \
        if (tid == 0 && (s) > 0 && (s) < S_STEPS - 1)                          \
            MBAR_EXPECT_TX((b) ? mb_l1 : mb_l0, 384);                          \
        /* prefetch x(s+2): consumed in step s+1's hidden window */            \
        float nx0 = 0.f, nx1 = 0.f, nx2 = 0.f;                                 \
        if ((s) + 2 < S_STEPS) {                                               \
            const float* xp = x + (size_t)((s) + 2) * 36 + chain;              \
            nx0 = __ldg(xp); nx1 = __ldg(xp + 12); nx2 = __ldg(xp + 24);       \
        }                                                                      \
        /* gates from carried z; computed on ALL lanes (c replicated) */       \
        float zi = __shfl_sync(fm, z, u8);                                     \
        float zf = __shfl_sync(fm, z, u8 + 8);                                 \
        float zg = __shfl_sync(fm, z, u8 + 16);                                \
        float zo = __shfl_sync(fm, z, u8 + 24);                                \
        float si = sigmoid_fast(zi);                                           \
        float sf = sigmoid_fast(zf);                                           \
        float so = sigmoid_fast(zo);                                           \
        c = sf * c + si * tanh_fast(zg);                                       \
        float hv = so * tanh_fast(c);                                          \
        /* fire remote sends ASAP: pair (h[2p], h[2p+1]) to rank dst */        \
        float ha = __shfl_sync(fm, hv, 2 * p_l);                               \
        float hb2 = __shfl_sync(fm, hv, 2 * p_l + 1);                          \
        if ((s) + 1 < S_STEPS && l < 12)                                       \
            st_async_b64(mybase + ((b) ? d_h1 : 0u), pack2(ha, hb2),           \
                         mybase + ((b) ? d_mb1 : d_mb0));                      \
        /* own h: plain local STS (no flight) */                               \
        if (l < 8) h_sh[b][ug] = hv;                                           \
        __syncthreads();                                                       \
        /* history STG in the hidden window (off the barrier-release path) */  \
        if (l < 8)                                                             \
            g_hhist[(size_t)((s) * NCH + chain) * HID + ug] = hv;              \
        if ((s) + 1 < S_STEPS) {                                               \
            /* hidden under flight: own-column partial (16 fma2) */            \
            const char* hb_ = (const char*)h_sh[b];                            \
            const ulonglong2* hl =                                             \
                reinterpret_cast<const ulonglong2*>(hb_ + rank * 128);         \
            unsigned long long a0 = 0ull, a1 = 0ull, a2 = 0ull, a3 = 0ull;     \
            _Pragma("unroll")                                                  \
            for (int k = 0; k < 8; k += 2) {                                   \
                ulonglong2 hA = hl[k];                                         \
                a0 = fma2(wl[k].x, hA.x, a0);                                  \
                a1 = fma2(wl[k].y, hA.y, a1);                                  \
                ulonglong2 hB = hl[k + 1];                                     \
                a2 = fma2(wl[k + 1].x, hB.x, a2);                              \
                a3 = fma2(wl[k + 1].y, hB.y, a3);                              \
            }                                                                  \
            /* prefold zown fully (unpack + x-term from xc) in hidden window */\
            float zown = unpack_sum(add2(add2(a0, a1), add2(a2, a3)))          \
                       + bsum + wx0 * xc0 + wx1 * xc1 + wx2 * xc2;             \
            /* wait for the 3 remote ranks' h (384B into mbar[b]) */           \
            if (b) { MBAR_WAIT(mb_l1, ph1); ph1 ^= 1; }                        \
            else   { MBAR_WAIT(mb_l0, ph0); ph0 ^= 1; }                        \
            /* remote 96 columns: 3 blocks x 16 fma2 */                        \
            unsigned long long a4 = 0ull, a5 = 0ull, a6 = 0ull, a7 = 0ull;     \
            _Pragma("unroll")                                                  \
            for (int j = 0; j < 3; j++) {                                      \
                const ulonglong2* hr =                                         \
                    reinterpret_cast<const ulonglong2*>(hb_ + ob[j]);          \
                _Pragma("unroll")                                              \
                for (int k = 0; k < 8; k += 2) {                               \
                    ulonglong2 hA = hr[k];                                     \
                    a4 = fma2(wr[j * 8 + k].x, hA.x, a4);                      \
                    a5 = fma2(wr[j * 8 + k].y, hA.y, a5);                      \
                    ulonglong2 hB = hr[k + 1];                                 \
                    a6 = fma2(wr[j * 8 + k + 1].x, hB.x, a6);                  \
                    a7 = fma2(wr[j * 8 + k + 1].y, hB.y, a7);                  \
                }                                                              \
            }                                                                  \
            z = zown + unpack_sum(add2(add2(a4, a5), add2(a6, a7)));           \
        }                                                                      \
        xc0 = nx0; xc1 = nx1; xc2 = nx2;                                       \
    }

    for (int s = 0; s < S_STEPS; s += 2) {
        LSTM_STEP(s, 0);
        LSTM_STEP(s + 1, 1);
    }
#undef LSTM_STEP
}

// Deferred output projection: out[row] = b_lin + h_hist[row,:] . W_lin
__global__ void __launch_bounds__(256) out_kernel(
    const float* __restrict__ Wlin, const float* __restrict__ blin,
    float* __restrict__ out)
{
    const int lane = threadIdx.x & 31;
    const int warp = (blockIdx.x * blockDim.x + threadIdx.x) >> 5;
    const float w0 = Wlin[lane],      w1 = Wlin[lane + 32];
    const float w2 = Wlin[lane + 64], w3 = Wlin[lane + 96];
    const float bl = __ldg(blin);
    int row = warp * 8;
#pragma unroll
    for (int k = 0; k < 8; k++, row++) {
        if (row >= NROWS_TOTAL) return;
        const float* h = g_hhist + (size_t)row * HID;
        float s = h[lane] * w0 + h[lane + 32] * w1
                + h[lane + 64] * w2 + h[lane + 96] * w3;
#pragma unroll
        for (int off = 16; off; off >>= 1)
            s += __shfl_xor_sync(0xffffffffu, s, off);
        if (lane == 0) out[row] = s + bl;
    }
}

extern "C" void kernel_launch(void* const* d_in, const int* in_sizes, int n_in,
                              void* d_out, int out_size)
{
    const float* x     = (const float*)d_in[0];
    const float* W_ih  = (const float*)d_in[1];
    const float* W_hh  = (const float*)d_in[2];
    const float* b_ih  = (const float*)d_in[3];
    const float* b_hh  = (const float*)d_in[4];
    const float* W_lin = (const float*)d_in[5];
    const float* b_lin = (const float*)d_in[6];
    float* out = (float*)d_out;

    lstm_kernel<<<12 * CLS, 128>>>(x, W_ih, W_hh, b_ih, b_hh);
    out_kernel<<<3684, 256>>>(W_lin, b_lin, out);
}

// round 17
// speedup vs baseline: 1.8689x; 1.0909x over previous
#include <cuda_runtime.h>
#include <cstdint>

#define S_STEPS 19648   // B*N = 64*307 sequential LSTM steps
#define NCH 12          // T_IN: independent LSTM chains
#define HID 128
#define CLS 4           // CTAs per chain (cluster size) — verified optimum
#define NROWS_TOTAL (S_STEPS * NCH)

// h history for deferred output projection: 19648*12*128 floats = ~115 MB
__device__ float g_hhist[(size_t)S_STEPS * NCH * HID];

// ---------------- PTX helpers ----------------
__device__ __forceinline__ uint32_t smem_u32(const void* p) {
    uint32_t a;
    asm("{ .reg .u64 t; cvta.to.shared.u64 t, %1; cvt.u32.u64 %0, t; }"
        : "=r"(a) : "l"(p));
    return a;
}
__device__ __forceinline__ uint32_t my_cluster_rank() {
    uint32_t r; asm("mov.u32 %0, %%cluster_ctarank;" : "=r"(r)); return r;
}
__device__ __forceinline__ uint32_t mapa_u32(uint32_t laddr, uint32_t rk) {
    uint32_t r;
    asm("mapa.shared::cluster.u32 %0, %1, %2;" : "=r"(r) : "r"(laddr), "r"(rk));
    return r;
}
// 8-byte remote shared store with mbarrier transaction tracking (proven R7 path).
__device__ __forceinline__ void st_async_b64(uint32_t raddr, unsigned long long v,
                                             uint32_t rmbar) {
    asm volatile(
        "st.async.shared::cluster.mbarrier::complete_tx::bytes.b64 [%0], %1, [%2];"
        :: "r"(raddr), "l"(v), "r"(rmbar) : "memory");
}
#define MBAR_INIT(a, n) \
    asm volatile("mbarrier.init.shared.b64 [%0], %1;" :: "r"(a), "r"((uint32_t)(n)) : "memory")
#define MBAR_EXPECT_TX(a, n) \
    asm volatile("mbarrier.arrive.expect_tx.shared.b64 _, [%0], %1;" :: "r"(a), "r"((uint32_t)(n)) : "memory")
// Proven wait: try_wait.parity.acquire carries st.async data visibility.
#define MBAR_WAIT(a, par) do {                                              \
    asm volatile(                                                           \
        "{\n\t.reg .pred P1;\n\t"                                           \
        "WL_%=:\n\t"                                                        \
        "mbarrier.try_wait.parity.acquire.cta.shared::cta.b64 P1, [%0], %1, 0x989680;\n\t" \
        "@P1 bra.uni WD_%=;\n\t"                                            \
        "bra.uni WL_%=;\n\t"                                                \
        "WD_%=:\n\t}"                                                       \
        :: "r"(a), "r"((uint32_t)(par)) : "memory");                        \
} while (0)

__device__ __forceinline__ unsigned long long fma2(unsigned long long a,
                                                   unsigned long long b,
                                                   unsigned long long c) {
    unsigned long long d;
    asm("fma.rn.f32x2 %0, %1, %2, %3;" : "=l"(d) : "l"(a), "l"(b), "l"(c));
    return d;
}
__device__ __forceinline__ unsigned long long add2(unsigned long long a,
                                                   unsigned long long b) {
    unsigned long long d;
    asm("add.rn.f32x2 %0, %1, %2;" : "=l"(d) : "l"(a), "l"(b));
    return d;
}
__device__ __forceinline__ float unpack_sum(unsigned long long a) {
    uint32_t lo, hi;
    asm("mov.b64 {%0, %1}, %2;" : "=r"(lo), "=r"(hi) : "l"(a));
    return __uint_as_float(lo) + __uint_as_float(hi);
}
__device__ __forceinline__ unsigned long long pack2(float lo, float hi) {
    unsigned long long d;
    asm("mov.b64 %0, {%1, %2};" : "=l"(d) : "f"(lo), "f"(hi));
    return d;
}
__device__ __forceinline__ float tanh_fast(float x) {
    float y; asm("tanh.approx.f32 %0, %1;" : "=f"(y) : "f"(x)); return y;
}
__device__ __forceinline__ float sigmoid_fast(float x) {
    return fmaf(0.5f, tanh_fast(0.5f * x), 0.5f);
}
#define CLUSTER_SYNC() do { \
    asm volatile("barrier.cluster.arrive.aligned;" ::: "memory"); \
    asm volatile("barrier.cluster.wait.aligned;"   ::: "memory"); } while (0)

// ---------------- LSTM kernel ----------------
// 48 CTAs = 12 chains x 4-CTA clusters, 128 threads/CTA (1 warp per SMSP).
// CTA rank r owns hidden units [32r, 32r+32); one FULL gate row per thread:
//   lane l: unit u8 = l&7 (warp w owns units 8w..8w+7), gate g = l>>3
// R7-proven step: gates from carried z -> h; lanes 0..11 send b64 unit-pairs
// to remote ranks BEFORE the local STS+bar; own-column partial hidden under
// the DSMEM flight; try_wait; remote 96 columns; z assembled at the tail.
// x is pipelined ONE EXTRA STEP (xc = x(s+1) loaded during step s-1; nx =
// x(s+2) loaded now). At NAT clock, L2 hit latency is ~420-470 cyc — the
// early x consumption in R8-R11 caused a ~280 cyc/step long-scoreboard
// stall. With xc the x-term NEVER stalls.
__global__ void __launch_bounds__(128, 1) __cluster_dims__(CLS, 1, 1)
lstm_kernel(const float* __restrict__ x,
            const float* __restrict__ W_ih,
            const float* __restrict__ W_hh,
            const float* __restrict__ b_ih,
            const float* __restrict__ b_hh)
{
    __shared__ __align__(16) float h_sh[2][HID];   // double-buffered hidden state
    __shared__ __align__(8)  unsigned long long mbar[2];

    const int tid  = threadIdx.x;
    const int w    = tid >> 5;
    const int l    = tid & 31;
    const int rank = (int)my_cluster_rank();
    const int chain = blockIdx.x / CLS;

    const int u8  = l & 7;                  // unit within warp's 8
    const int g   = l >> 3;                 // gate 0..3 (i,f,g,o)
    const int ug  = 32 * rank + 8 * w + u8; // global hidden unit
    const int row = g * 128 + ug;           // row in W (4H x H)

    // Register-resident W_hh row, split: own 32 cols (wl) / remote 96 (wr),
    // wr ordered by remote rank j=0..2 -> rk=(rank+1+j)&3, cols [32rk,32rk+32)
    const ulonglong2* wp =
        reinterpret_cast<const ulonglong2*>(W_hh + (size_t)row * HID);
    ulonglong2 wl[8], wr[24];
    int ob[3];  // byte offsets of remote column blocks within h row
#pragma unroll
    for (int k = 0; k < 8; k++) wl[k] = wp[rank * 8 + k];
#pragma unroll
    for (int j = 0; j < 3; j++) {
        const int rk = (rank + 1 + j) & 3;
        ob[j] = rk * 128;  // 32 floats * 4B
#pragma unroll
        for (int k = 0; k < 8; k++) wr[j * 8 + k] = wp[rk * 8 + k];
    }

    const float wx0 = W_ih[row * 3 + 0];
    const float wx1 = W_ih[row * 3 + 1];
    const float wx2 = W_ih[row * 3 + 2];
    const float bsum = b_ih[row] + b_hh[row];

    h_sh[0][tid] = 0.f;   // 128 threads cover all 128 h

    const uint32_t mb_l0 = smem_u32(&mbar[0]);
    const uint32_t mb_l1 = smem_u32(&mbar[1]);
    if (tid == 0) {
        MBAR_INIT(mb_l0, 1);
        MBAR_INIT(mb_l1, 1);
        MBAR_EXPECT_TX(mb_l1, 384);   // step-0 sends target buffer/mbar 1
    }
    __syncthreads();   // local h zeros + mbar init done
    CLUSTER_SYNC();    // mbar init visible cluster-wide before any st.async

    // Send targets (lanes 0..11): pair p=l&3 of this warp's units -> remote
    // rank j=l>>2 (dst = (rank+1+j)&3). Buffer-1/mbar addrs by const deltas.
    const int p_l = l & 3;
    const int dst = (rank + 1 + (l >> 2)) & 3;
    const uint32_t la_pair = smem_u32(&h_sh[0][32 * rank + 8 * w + 2 * p_l]);
    const uint32_t mybase  = mapa_u32(la_pair, (uint32_t)dst);
    const uint32_t d_h1    = (uint32_t)(HID * sizeof(float));
    const uint32_t d_mb0   = mb_l0 - la_pair;
    const uint32_t d_mb1   = mb_l1 - la_pair;

    float c = 0.f;        // cell state (replicated across lanes; valid for u8)
    int ph0 = 0, ph1 = 0; // mbarrier phase parities
    const unsigned fm = 0xffffffffu;

    // Step-0 pre-activation: h(-1)=0, so z = bsum + W_ih . x(0)
    float z = bsum + wx0 * x[chain] + wx1 * x[12 + chain] + wx2 * x[24 + chain];

    // Carried x for step 1 (used at the tail of step 0) — one full step of slack
    float xc0 = 0.f, xc1 = 0.f, xc2 = 0.f;
    {
        const float* xp = x + 36 + chain;
        xc0 = __ldg(xp); xc1 = __ldg(xp + 12); xc2 = __ldg(xp + 24);
    }

#define LSTM_STEP(s, P)                                                        \
    {                                                                          \
        const int b = 1 - (P);                                                 \
        if (tid == 0 && (s) > 0 && (s) < S_STEPS - 1)                          \
            MBAR_EXPECT_TX((b) ? mb_l1 : mb_l0, 384);                          \
        /* prefetch x(s+2): consumed at the tail of step s+1 (~1.2K cyc) */    \
        float nx0 = 0.f, nx1 = 0.f, nx2 = 0.f;                                 \
        if ((s) + 2 < S_STEPS) {                                               \
            const float* xp = x + (size_t)((s) + 2) * 36 + chain;              \
            nx0 = __ldg(xp); nx1 = __ldg(xp + 12); nx2 = __ldg(xp + 24);       \
        }                                                                      \
        /* gates from carried z; computed on ALL lanes (c replicated) */       \
        float zi = __shfl_sync(fm, z, u8);                                     \
        float zf = __shfl_sync(fm, z, u8 + 8);                                 \
        float zg = __shfl_sync(fm, z, u8 + 16);                                \
        float zo = __shfl_sync(fm, z, u8 + 24);                                \
        float si = sigmoid_fast(zi);                                           \
        float sf = sigmoid_fast(zf);                                           \
        float so = sigmoid_fast(zo);                                           \
        c = sf * c + si * tanh_fast(zg);                                       \
        float hv = so * tanh_fast(c);                                          \
        /* fire remote sends ASAP: pair (h[2p], h[2p+1]) to rank dst */        \
        float ha = __shfl_sync(fm, hv, 2 * p_l);                               \
        float hb2 = __shfl_sync(fm, hv, 2 * p_l + 1);                          \
        if ((s) + 1 < S_STEPS && l < 12)                                       \
            st_async_b64(mybase + ((b) ? d_h1 : 0u), pack2(ha, hb2),           \
                         mybase + ((b) ? d_mb1 : d_mb0));                      \
        /* own h: plain local STS (no flight) + history store */               \
        if (l < 8) {                                                           \
            h_sh[b][ug] = hv;                                                  \
            g_hhist[(size_t)((s) * NCH + chain) * HID + ug] = hv;              \
        }                                                                      \
        __syncthreads();                                                       \
        if ((s) + 1 < S_STEPS) {                                               \
            /* own-column partial while remote h is in flight: 16 fma2 */      \
            const char* hb_ = (const char*)h_sh[b];                            \
            const ulonglong2* hl =                                             \
                reinterpret_cast<const ulonglong2*>(hb_ + rank * 128);         \
            unsigned long long a0 = 0ull, a1 = 0ull, a2 = 0ull, a3 = 0ull;     \
            _Pragma("unroll")                                                  \
            for (int k = 0; k < 8; k += 2) {                                   \
                ulonglong2 hA = hl[k];                                         \
                a0 = fma2(wl[k].x, hA.x, a0);                                  \
                a1 = fma2(wl[k].y, hA.y, a1);                                  \
                ulonglong2 hB = hl[k + 1];                                     \
                a2 = fma2(wl[k + 1].x, hB.x, a2);                              \
                a3 = fma2(wl[k + 1].y, hB.y, a3);                              \
            }                                                                  \
            /* wait for the 3 remote ranks' h (384B into mbar[b]) */           \
            if (b) { MBAR_WAIT(mb_l1, ph1); ph1 ^= 1; }                        \
            else   { MBAR_WAIT(mb_l0, ph0); ph0 ^= 1; }                        \
            /* remote 96 columns: 3 blocks x 16 fma2 */                        \
            unsigned long long a4 = 0ull, a5 = 0ull, a6 = 0ull, a7 = 0ull;     \
            _Pragma("unroll")                                                  \
            for (int j = 0; j < 3; j++) {                                      \
                const ulonglong2* hr =                                         \
                    reinterpret_cast<const ulonglong2*>(hb_ + ob[j]);          \
                _Pragma("unroll")                                              \
                for (int k = 0; k < 8; k += 2) {                               \
                    ulonglong2 hA = hr[k];                                     \
                    a4 = fma2(wr[j * 8 + k].x, hA.x, a4);                      \
                    a5 = fma2(wr[j * 8 + k].y, hA.y, a5);                      \
                    ulonglong2 hB = hr[k + 1];                                 \
                    a6 = fma2(wr[j * 8 + k + 1].x, hB.x, a6);                  \
                    a7 = fma2(wr[j * 8 + k + 1].y, hB.y, a7);                  \
                }                                                              \
            }                                                                  \
            unsigned long long t0 = add2(add2(a0, a1), add2(a2, a3));          \
            unsigned long long t1 = add2(add2(a4, a5), add2(a6, a7));          \
            /* x-term from xc (loaded a FULL step ago -> zero stall) */        \
            z = unpack_sum(add2(t0, t1))                                       \
              + bsum + wx0 * xc0 + wx1 * xc1 + wx2 * xc2;                      \
        }                                                                      \
        xc0 = nx0; xc1 = nx1; xc2 = nx2;                                       \
    }

    for (int s = 0; s < S_STEPS; s += 2) {
        LSTM_STEP(s, 0);
        LSTM_STEP(s + 1, 1);
    }
#undef LSTM_STEP
}

// Deferred output projection: out[row] = b_lin + h_hist[row,:] . W_lin
__global__ void __launch_bounds__(256) out_kernel(
    const float* __restrict__ Wlin, const float* __restrict__ blin,
    float* __restrict__ out)
{
    const int lane = threadIdx.x & 31;
    const int warp = (blockIdx.x * blockDim.x + threadIdx.x) >> 5;
    const float w0 = Wlin[lane],      w1 = Wlin[lane + 32];
    const float w2 = Wlin[lane + 64], w3 = Wlin[lane + 96];
    const float bl = __ldg(blin);
    int row = warp * 8;
#pragma unroll
    for (int k = 0; k < 8; k++, row++) {
        if (row >= NROWS_TOTAL) return;
        const float* h = g_hhist + (size_t)row * HID;
        float s = h[lane] * w0 + h[lane + 32] * w1
                + h[lane + 64] * w2 + h[lane + 96] * w3;
#pragma unroll
        for (int off = 16; off; off >>= 1)
            s += __shfl_xor_sync(0xffffffffu, s, off);
        if (lane == 0) out[row] = s + bl;
    }
}

extern "C" void kernel_launch(void* const* d_in, const int* in_sizes, int n_in,
                              void* d_out, int out_size)
{
    const float* x     = (const float*)d_in[0];
    const float* W_ih  = (const float*)d_in[1];
    const float* W_hh  = (const float*)d_in[2];
    const float* b_ih  = (const float*)d_in[3];
    const float* b_hh  = (const float*)d_in[4];
    const float* W_lin = (const float*)d_in[5];
    const float* b_lin = (const float*)d_in[6];
    float* out = (float*)d_out;

    lstm_kernel<<<12 * CLS, 128>>>(x, W_ih, W_hh, b_ih, b_hh);
    out_kernel<<<3684, 256>>>(W_lin, b_lin, out);
}